// round 10
// baseline (speedup 1.0000x reference)
#include <cuda_runtime.h>
#include <cuda_bf16.h>

// ---------------------------------------------------------------------------
// QNN: batched 4-qubit circuit + Linear(4,6) + softmax.
// Round 10 (= Round 8 kernel, resubmitted through infra failures):
// f32x2-packed math (2 samples/thread) with measured-overhead fixes:
//   * coefficients pre-packed as u64 pairs in prep kernel -> single LDS.64 use
//   * linear layer + softmax numerators packed (24 fma2 vs 48 scalar FMA)
//   * direct v2 global stores (every 24B sample slot is 8B aligned);
//     obuf smem staging and the second barrier removed
// Index convention: idx = q0*8 + q1*4 + q2*2 + q3  (qubit i at bit 3-i).
// ---------------------------------------------------------------------------

typedef unsigned long long u64;

struct ParamsP {
    float w0[4];                 // layer-0 weight angles (folded into x)
    u64 c1[4], s1[4], ns1[4];    // packed (c,c) (s,s) (-s,-s) of 0.5*w1
    u64 c2[4], s2[4], ns2[4];    // same for 0.5*w2
    u64 W2[6][4];                // packed (W[j][i], W[j][i])
    u64 b2[6];                   // packed (b[j], b[j])
};

__device__ ParamsP g_params;

__device__ __forceinline__ u64 pk(float lo, float hi) {
    u64 r; asm("mov.b64 %0, {%1, %2};" : "=l"(r) : "f"(lo), "f"(hi)); return r;
}
__device__ __forceinline__ void upk(u64 v, float& lo, float& hi) {
    asm("mov.b64 {%0, %1}, %2;" : "=f"(lo), "=f"(hi) : "l"(v));
}
__device__ __forceinline__ u64 fma2(u64 a, u64 b, u64 c) {
    u64 d; asm("fma.rn.f32x2 %0, %1, %2, %3;" : "=l"(d) : "l"(a), "l"(b), "l"(c)); return d;
}
__device__ __forceinline__ u64 mul2(u64 a, u64 b) {
    u64 d; asm("mul.rn.f32x2 %0, %1, %2;" : "=l"(d) : "l"(a), "l"(b)); return d;
}
__device__ __forceinline__ u64 add2(u64 a, u64 b) {
    u64 d; asm("add.rn.f32x2 %0, %1, %2;" : "=l"(d) : "l"(a), "l"(b)); return d;
}

__global__ void prep_kernel(const float* __restrict__ qw,   // (3,4)
                            const float* __restrict__ W,    // (6,4)
                            const float* __restrict__ b)    // (6,)
{
    if (threadIdx.x == 0 && blockIdx.x == 0) {
        #pragma unroll
        for (int i = 0; i < 4; i++) g_params.w0[i] = qw[i];
        #pragma unroll
        for (int i = 0; i < 4; i++) {
            float h = 0.5f * qw[4 + i];
            float c = cosf(h), s = sinf(h);
            g_params.c1[i]  = pk(c, c);
            g_params.s1[i]  = pk(s, s);
            g_params.ns1[i] = pk(-s, -s);
        }
        #pragma unroll
        for (int i = 0; i < 4; i++) {
            float h = 0.5f * qw[8 + i];
            float c = cosf(h), s = sinf(h);
            g_params.c2[i]  = pk(c, c);
            g_params.s2[i]  = pk(s, s);
            g_params.ns2[i] = pk(-s, -s);
        }
        for (int j = 0; j < 6; j++) {
            for (int i = 0; i < 4; i++) {
                float w = W[j * 4 + i];
                g_params.W2[j][i] = pk(w, w);
            }
            g_params.b2[j] = pk(b[j], b[j]);
        }
    }
}

// CNOT ring: pure compile-time index permutation on packed amplitudes.
__device__ __forceinline__ void apply_cnot_ring(u64* __restrict__ psi)
{
    u64 t[16];
    #pragma unroll
    for (int i = 0; i < 16; i++) t[i] = psi[((i >> 3) & 1) ? (i ^ 4) : i];   // CNOT(0,1)
    u64 t2[16];
    #pragma unroll
    for (int i = 0; i < 16; i++) t2[i] = t[((i >> 2) & 1) ? (i ^ 2) : i];    // CNOT(1,2)
    #pragma unroll
    for (int i = 0; i < 16; i++) t[i] = t2[((i >> 1) & 1) ? (i ^ 1) : i];    // CNOT(2,3)
    #pragma unroll
    for (int i = 0; i < 16; i++) psi[i] = t[(i & 1) ? (i ^ 8) : i];          // CNOT(3,0)
}

// Packed RY layer; coefficients come pre-packed from smem (LDS.64 each).
__device__ __forceinline__ void apply_ry_layer2(u64* __restrict__ psi,
                                                const u64* __restrict__ cv,
                                                const u64* __restrict__ sv,
                                                const u64* __restrict__ nsv)
{
    #pragma unroll
    for (int q = 0; q < 4; q++) {
        const int m = 1 << (3 - q);
        const u64 c2q  = cv[q];
        const u64 s2q  = sv[q];
        const u64 ns2q = nsv[q];
        #pragma unroll
        for (int i = 0; i < 16; i++) {
            if (!(i & m)) {
                u64 a0 = psi[i];
                u64 a1 = psi[i | m];
                psi[i]     = fma2(c2q, a0, mul2(ns2q, a1));  // c*a0 - s*a1
                psi[i | m] = fma2(s2q, a0, mul2(c2q,  a1));  // s*a0 + c*a1
            }
        }
    }
}

__global__ __launch_bounds__(128) void qnn_kernel(const float4* __restrict__ x,
                                                  float2* __restrict__ out,
                                                  int B)
{
    __shared__ ParamsP sp;

    // stage uniform params into shared (one barrier for the whole kernel)
    {
        constexpr int NW = sizeof(ParamsP) / 4;
        #pragma unroll
        for (int w = threadIdx.x; w < NW; w += 128)
            ((float*)&sp)[w] = ((const float*)&g_params)[w];
    }
    __syncthreads();

    const int tid  = threadIdx.x;
    const int base = blockIdx.x * 256;
    const int s0   = base + tid;
    const int s1   = s0 + 128;

    float4 xv0 = (s0 < B) ? x[s0] : make_float4(0.f, 0.f, 0.f, 0.f);
    float4 xv1 = (s1 < B) ? x[s1] : make_float4(0.f, 0.f, 0.f, 0.f);

    // half-angle sincos per sample (layer-0 weights folded in)
    float ca[4], sa[4], cb[4], sb[4];
    __sincosf(0.5f * (xv0.x + sp.w0[0]), &sa[0], &ca[0]);
    __sincosf(0.5f * (xv0.y + sp.w0[1]), &sa[1], &ca[1]);
    __sincosf(0.5f * (xv0.z + sp.w0[2]), &sa[2], &ca[2]);
    __sincosf(0.5f * (xv0.w + sp.w0[3]), &sa[3], &ca[3]);
    __sincosf(0.5f * (xv1.x + sp.w0[0]), &sb[0], &cb[0]);
    __sincosf(0.5f * (xv1.y + sp.w0[1]), &sb[1], &cb[1]);
    __sincosf(0.5f * (xv1.z + sp.w0[2]), &sb[2], &cb[2]);
    __sincosf(0.5f * (xv1.w + sp.w0[3]), &sb[3], &cb[3]);

    // pack the two samples lane-wise
    u64 c2[4], s2v[4];
    #pragma unroll
    for (int i = 0; i < 4; i++) {
        c2[i]  = pk(ca[i], cb[i]);
        s2v[i] = pk(sa[i], sb[i]);
    }

    // product state: psi[b0b1b2b3] = f0(b0) f1(b1) f2(b2) f3(b3)
    u64 u2[4], v2[4];
    u2[0] = mul2(c2[0],  c2[1]);  u2[1] = mul2(c2[0],  s2v[1]);
    u2[2] = mul2(s2v[0], c2[1]);  u2[3] = mul2(s2v[0], s2v[1]);
    v2[0] = mul2(c2[2],  c2[3]);  v2[1] = mul2(c2[2],  s2v[3]);
    v2[2] = mul2(s2v[2], c2[3]);  v2[3] = mul2(s2v[2], s2v[3]);

    u64 psi[16];
    #pragma unroll
    for (int a = 0; a < 4; a++)
        #pragma unroll
        for (int bb = 0; bb < 4; bb++)
            psi[a * 4 + bb] = mul2(u2[a], v2[bb]);

    // circuit: ring, RY(w1), ring, RY(w2)
    apply_cnot_ring(psi);
    apply_ry_layer2(psi, sp.c1, sp.s1, sp.ns1);
    apply_cnot_ring(psi);
    apply_ry_layer2(psi, sp.c2, sp.s2, sp.ns2);

    // probabilities
    u64 p[16];
    #pragma unroll
    for (int i = 0; i < 16; i++) p[i] = mul2(psi[i], psi[i]);

    // <Z_w> butterfly (packed); sub via fma2(neg1, y, x)
    const u64 neg1 = pk(-1.f, -1.f);
    u64 A[8], D[8];
    #pragma unroll
    for (int j = 0; j < 8; j++) {
        A[j] = add2(p[j], p[j + 8]);
        D[j] = fma2(neg1, p[j + 8], p[j]);
    }
    u64 E0 = add2(add2(add2(D[0], D[1]), add2(D[2], D[3])),
                  add2(add2(D[4], D[5]), add2(D[6], D[7])));
    u64 sA01 = add2(A[0], A[1]), sA23 = add2(A[2], A[3]);
    u64 sA45 = add2(A[4], A[5]), sA67 = add2(A[6], A[7]);
    u64 E1 = fma2(neg1, add2(sA45, sA67), add2(sA01, sA23));
    u64 E2 = fma2(neg1, add2(sA23, sA67), add2(sA01, sA45));
    u64 sE  = add2(add2(A[0], A[2]), add2(A[4], A[6]));
    u64 sO  = add2(add2(A[1], A[3]), add2(A[5], A[7]));
    u64 E3 = fma2(neg1, sO, sE);

    // Linear(4,6) packed: L_j = b_j + sum_i E_i * W[j][i]  (both samples at once)
    float exa[6], exb[6];
    #pragma unroll
    for (int j = 0; j < 6; j++) {
        u64 L = sp.b2[j];
        L = fma2(E0, sp.W2[j][0], L);
        L = fma2(E1, sp.W2[j][1], L);
        L = fma2(E2, sp.W2[j][2], L);
        L = fma2(E3, sp.W2[j][3], L);
        float la, lb;
        upk(L, la, lb);
        exa[j] = __expf(la);
        exb[j] = __expf(lb);
    }
    float dena = ((exa[0] + exa[1]) + (exa[2] + exa[3])) + (exa[4] + exa[5]);
    float denb = ((exb[0] + exb[1]) + (exb[2] + exb[3])) + (exb[4] + exb[5]);
    float inva = __fdividef(1.0f, dena);
    float invb = __fdividef(1.0f, denb);

    // direct v2 stores: sample s owns out float2 slots [3s, 3s+3)
    if (s0 < B) {
        long long o = 3LL * s0;
        out[o + 0] = make_float2(exa[0] * inva, exa[1] * inva);
        out[o + 1] = make_float2(exa[2] * inva, exa[3] * inva);
        out[o + 2] = make_float2(exa[4] * inva, exa[5] * inva);
    }
    if (s1 < B) {
        long long o = 3LL * s1;
        out[o + 0] = make_float2(exb[0] * invb, exb[1] * invb);
        out[o + 1] = make_float2(exb[2] * invb, exb[3] * invb);
        out[o + 2] = make_float2(exb[4] * invb, exb[5] * invb);
    }
}

extern "C" void kernel_launch(void* const* d_in, const int* in_sizes, int n_in,
                              void* d_out, int out_size)
{
    const float* x  = (const float*)d_in[0];   // (B,4)
    const float* qw = (const float*)d_in[1];   // (3,4)
    const float* W  = (const float*)d_in[2];   // (6,4)
    const float* b  = (const float*)d_in[3];   // (6,)
    float2* out = (float2*)d_out;              // (B,6) viewed as (B*3) float2

    const int B = in_sizes[0] / 4;

    prep_kernel<<<1, 32>>>(qw, W, b);
    const int blocks = (B + 255) / 256;        // 256 samples per block
    qnn_kernel<<<blocks, 128>>>((const float4*)x, out, B);
}